// round 3
// baseline (speedup 1.0000x reference)
#include <cuda_runtime.h>
#include <math.h>

#define BATCH 4
#define CH 64
#define NPIX 4096
#define NB 8192
#define S_REFINE_T 64.0

// ---------------- scratch (device globals; no allocs allowed) ----------------
__device__ float    g_a[BATCH][NPIX];
__device__ float    g_d[BATCH][NPIX];
__device__ unsigned g_mm[BATCH][2];            // encoded min/max of a per batch
__device__ int      g_binstart[BATCH][NB + 1];
__device__ int      g_perm[BATCH][NPIX];
__device__ float    g_u[CH];
__device__ float    g_w[CH];
__device__ float    g_cacd[2];
__device__ double   g_wd[CH];                  // double-folded wck.Wk
__device__ double   g_cd;                      // double wck.bk
__device__ float    g_Mt[CH * CH];             // M^T: [c][o], M = Wg @ Wv
__device__ float    g_g0[CH];                  // Wg@bv/1.5 + bg

// sorted-order per-element values (double)
__device__ double   g_as[BATCH][NPIX];
__device__ double   g_es[BATCH][NPIX];
// scalar exclusive prefixes over sorted order (index 0..NPIX; [NPIX] = total)
__device__ double   g_PAs[BATCH][NPIX + 1];
__device__ double   g_PEs[BATCH][NPIX + 1];
// vector exclusive prefixes: [b][r][c], r = 0..NPIX ([NPIX] = totals)
__device__ double   g_P1[BATCH][NPIX + 1][CH];
__device__ double   g_PA[BATCH][NPIX + 1][CH];
__device__ double   g_PE[BATCH][NPIX + 1][CH];

// ---------------- helpers ----------------
__device__ __forceinline__ unsigned fenc(float f) {
    unsigned u = __float_as_uint(f);
    return (u & 0x80000000u) ? ~u : (u | 0x80000000u);
}
__device__ __forceinline__ float fdec(unsigned e) {
    unsigned u = (e & 0x80000000u) ? (e & 0x7fffffffu) : ~e;
    return __uint_as_float(u);
}
__device__ __forceinline__ float binScale(float lo, float hi) {
    return (float)NB / (hi - lo + 1e-6f);
}

// block-wide exclusive scan of 2 doubles; requires blockDim.x == 1024
__device__ __forceinline__ void blockScan2(double v1, double v2,
                                           double& e1, double& e2,
                                           double& T1, double& T2) {
    int lane = threadIdx.x & 31, wid = threadIdx.x >> 5;
    __shared__ double ws[2][32];
    double i1 = v1, i2 = v2;
#pragma unroll
    for (int off = 1; off < 32; off <<= 1) {
        double n1 = __shfl_up_sync(0xffffffffu, i1, off);
        double n2 = __shfl_up_sync(0xffffffffu, i2, off);
        if (lane >= off) { i1 += n1; i2 += n2; }
    }
    if (lane == 31) { ws[0][wid] = i1; ws[1][wid] = i2; }
    __syncthreads();
    if (wid == 0) {
        double a = ws[0][lane], b2 = ws[1][lane];
#pragma unroll
        for (int off = 1; off < 32; off <<= 1) {
            double n1 = __shfl_up_sync(0xffffffffu, a, off);
            double n2 = __shfl_up_sync(0xffffffffu, b2, off);
            if (lane >= off) { a += n1; b2 += n2; }
        }
        ws[0][lane] = a; ws[1][lane] = b2;
    }
    __syncthreads();
    double w1 = wid ? ws[0][wid - 1] : 0.0;
    double w2 = wid ? ws[1][wid - 1] : 0.0;
    e1 = (i1 - v1) + w1; e2 = (i2 - v2) + w2;
    T1 = ws[0][31]; T2 = ws[1][31];
}

// ---------------- k_prep: fold weights -------------------------------------
__global__ void k_prep(const float* __restrict__ Wq, const float* __restrict__ bq,
                       const float* __restrict__ Wk, const float* __restrict__ bk,
                       const float* __restrict__ wcq, const float* __restrict__ wck,
                       const float* __restrict__ Wv, const float* __restrict__ bv,
                       const float* __restrict__ Wg, const float* __restrict__ bg) {
    int blk = blockIdx.x, t = threadIdx.x;
    if (blk < CH) {
        int o = blk;
        float acc = 0.f;
#pragma unroll 16
        for (int k = 0; k < CH; k++) acc += Wg[o * CH + k] * Wv[k * CH + t];
        g_Mt[t * CH + o] = acc;
        if (t == 0) {
            float s = 0.f;
            for (int k = 0; k < CH; k++) s += Wg[o * CH + k] * bv[k];
            g_g0[o] = s * (1.f / 1.5f) + bg[o];
        }
    } else {
        float su = 0.f;
        double swd = 0.0;
#pragma unroll
        for (int o2 = 0; o2 < 16; o2++) {
            su  += wcq[o2] * Wq[o2 * CH + t];
            swd += (double)wck[o2] * (double)Wk[o2 * CH + t];
        }
        g_u[t] = su; g_w[t] = (float)swd; g_wd[t] = swd;
        if (t == 0) {
            float ca = 0.f;
            double cdd = 0.0;
            for (int o2 = 0; o2 < 16; o2++) {
                ca += wcq[o2] * bq[o2];
                cdd += (double)wck[o2] * (double)bk[o2];
            }
            g_cacd[0] = ca; g_cacd[1] = (float)cdd; g_cd = cdd;
            for (int b = 0; b < BATCH; b++) { g_mm[b][0] = 0xFFFFFFFFu; g_mm[b][1] = 0u; }
        }
    }
}

// ---------------- k_ad: a[b,n], d[b,n] + per-batch min/max of a -------------
__global__ void __launch_bounds__(256) k_ad(const float* __restrict__ x) {
    __shared__ float su[CH], sw[CH];
    __shared__ float redmin[8], redmax[8];
    int t = threadIdx.x;
    if (t < CH) { su[t] = g_u[t]; sw[t] = g_w[t]; }
    __syncthreads();
    int gid = blockIdx.x * 256 + t;
    int b = gid >> 12, n = gid & (NPIX - 1);
    const float* xb = x + ((size_t)b * CH) * NPIX + n;
    float au = 0.f, dv = 0.f;
#pragma unroll
    for (int c = 0; c < CH; c++) {
        float xv = xb[(size_t)c * NPIX];
        au += su[c] * xv;
        dv += sw[c] * xv;
    }
    float a = au + g_cacd[0];
    float d = dv + g_cacd[1];
    g_a[b][n] = a; g_d[b][n] = d;
    float mn = a, mx = a;
#pragma unroll
    for (int off = 16; off; off >>= 1) {
        mn = fminf(mn, __shfl_xor_sync(0xffffffffu, mn, off));
        mx = fmaxf(mx, __shfl_xor_sync(0xffffffffu, mx, off));
    }
    int lane = t & 31, wid = t >> 5;
    if (lane == 0) { redmin[wid] = mn; redmax[wid] = mx; }
    __syncthreads();
    if (t == 0) {
        for (int i = 1; i < 8; i++) { mn = fminf(mn, redmin[i]); mx = fmaxf(mx, redmax[i]); }
        atomicMin(&g_mm[b][0], fenc(mn));
        atomicMax(&g_mm[b][1], fenc(mx));
    }
}

// ---------------- k_sort: counting sort of a per batch into 8192 bins -------
__global__ void __launch_bounds__(1024, 1) k_sort() {
    __shared__ unsigned bins[NB];
    __shared__ unsigned wsum[32];
    int b = blockIdx.x, t = threadIdx.x;
    int lane = t & 31, wid = t >> 5;
    for (int i = t; i < NB; i += 1024) bins[i] = 0u;
    __syncthreads();
    float lo = fdec(g_mm[b][0]), hi = fdec(g_mm[b][1]);
    float scale = binScale(lo, hi);
    for (int i = t; i < NPIX; i += 1024) {
        float a = g_a[b][i];
        int e = (int)floorf((a - lo) * scale);
        e = e < 0 ? 0 : (e > NB - 1 ? NB - 1 : e);
        atomicAdd(&bins[e], 1u);
    }
    __syncthreads();
    unsigned vals[8]; unsigned tsum = 0;
    int base = t * 8;
#pragma unroll
    for (int q = 0; q < 8; q++) { vals[q] = bins[base + q]; tsum += vals[q]; }
    unsigned inc = tsum;
#pragma unroll
    for (int off = 1; off < 32; off <<= 1) {
        unsigned nv = __shfl_up_sync(0xffffffffu, inc, off);
        if (lane >= off) inc += nv;
    }
    if (lane == 31) wsum[wid] = inc;
    __syncthreads();
    if (wid == 0) {
        unsigned ia = wsum[lane];
#pragma unroll
        for (int off = 1; off < 32; off <<= 1) {
            unsigned nv = __shfl_up_sync(0xffffffffu, ia, off);
            if (lane >= off) ia += nv;
        }
        wsum[lane] = ia;
    }
    __syncthreads();
    unsigned run = (wid ? wsum[wid - 1] : 0u) + (inc - tsum);
#pragma unroll
    for (int q = 0; q < 8; q++) {
        g_binstart[b][base + q] = (int)run;
        bins[base + q] = run;
        run += vals[q];
    }
    if (t == 0) g_binstart[b][NB] = NPIX;
    __syncthreads();
    for (int i = t; i < NPIX; i += 1024) {
        float a = g_a[b][i];
        int e = (int)floorf((a - lo) * scale);
        e = e < 0 ? 0 : (e > NB - 1 ? NB - 1 : e);
        unsigned pos = atomicAdd(&bins[e], 1u);
        g_perm[b][pos] = i;
    }
}

// ---------------- k_scan_scalar: sorted a/e^a + scalar prefixes -------------
__global__ void __launch_bounds__(1024, 1) k_scan_scalar() {
    int b = blockIdx.x, t = threadIdx.x;
    int r0 = t * 4;
    double av[4], ev[4];
#pragma unroll
    for (int i = 0; i < 4; i++) {
        int r = r0 + i;
        int p = g_perm[b][r];
        double a = (double)g_a[b][p];
        double e = exp(a);
        av[i] = a; ev[i] = e;
        g_as[b][r] = a; g_es[b][r] = e;
    }
    double ta = 0, te = 0;
#pragma unroll
    for (int i = 0; i < 4; i++) { ta += av[i]; te += ev[i]; }
    double ea, ee, Ta, Te;
    blockScan2(ta, te, ea, ee, Ta, Te);
    double ra = ea, re = ee;
#pragma unroll
    for (int i = 0; i < 4; i++) {
        int r = r0 + i;
        g_PAs[b][r] = ra;
        g_PEs[b][r] = re;
        ra += av[i]; re += ev[i];
    }
    if (t == 1023) { g_PAs[b][NPIX] = ra; g_PEs[b][NPIX] = re; }
}

// ---------------- k_scan_vec: 64-dim prefix vectors over sorted order -------
// grid (16 cgroups, BATCH); block 1024 = 4 c_sub (interleaved in lanes) x 256 idx
__global__ void __launch_bounds__(1024, 1) k_scan_vec(const float* __restrict__ x) {
    __shared__ double wt[3][4][32];
    int b = blockIdx.y, cg = blockIdx.x;
    int t = threadIdx.x;
    int c_sub = t & 3, idx = t >> 2;
    int c = cg * 4 + c_sub;
    int r0 = idx * 16;
    int lane = t & 31, w = t >> 5;
    const float* xrow = x + ((size_t)(b * CH + c)) * NPIX;

    float xs[16];
    double s1 = 0, sa = 0, se = 0;
#pragma unroll
    for (int i = 0; i < 16; i++) {
        int r = r0 + i;
        int p = g_perm[b][r];
        float xv = xrow[p];
        xs[i] = xv;
        double a = g_as[b][r];
        double e = g_es[b][r];
        double xd = (double)xv;
        s1 += xd; sa += xd * a; se += xd * e;
    }
    double i1 = s1, ia = sa, ie = se;
#pragma unroll
    for (int off = 4; off < 32; off <<= 1) {
        double n1 = __shfl_up_sync(0xffffffffu, i1, off);
        double n2 = __shfl_up_sync(0xffffffffu, ia, off);
        double n3 = __shfl_up_sync(0xffffffffu, ie, off);
        if (lane >= off) { i1 += n1; ia += n2; ie += n3; }
    }
    if (lane >= 28) {
        wt[0][lane & 3][w] = i1;
        wt[1][lane & 3][w] = ia;
        wt[2][lane & 3][w] = ie;
    }
    __syncthreads();
    if (w < 4) {
        double a0 = wt[0][w][lane], a1 = wt[1][w][lane], a2 = wt[2][w][lane];
#pragma unroll
        for (int off = 1; off < 32; off <<= 1) {
            double n0 = __shfl_up_sync(0xffffffffu, a0, off);
            double n1 = __shfl_up_sync(0xffffffffu, a1, off);
            double n2 = __shfl_up_sync(0xffffffffu, a2, off);
            if (lane >= off) { a0 += n0; a1 += n1; a2 += n2; }
        }
        wt[0][w][lane] = a0; wt[1][w][lane] = a1; wt[2][w][lane] = a2;
    }
    __syncthreads();
    double b1 = (w ? wt[0][c_sub][w - 1] : 0.0) + (i1 - s1);
    double ba = (w ? wt[1][c_sub][w - 1] : 0.0) + (ia - sa);
    double be = (w ? wt[2][c_sub][w - 1] : 0.0) + (ie - se);

    double r1 = b1, ra = ba, re = be;
#pragma unroll
    for (int i = 0; i < 16; i++) {
        int r = r0 + i;
        g_P1[b][r][c] = r1;
        g_PA[b][r][c] = ra;
        g_PE[b][r][c] = re;
        double a = g_as[b][r];
        double e = g_es[b][r];
        double xd = (double)xs[i];
        r1 += xd; ra += xd * a; re += xd * e;
    }
    if (idx == 255) {
        g_P1[b][NPIX][c] = r1;
        g_PA[b][NPIX][c] = ra;
        g_PE[b][NPIX][c] = re;
    }
}

// ---------------- k_y_out: split lookup + y + fused 64x64 GEMM --------------
// grid (NPIX/32, BATCH); block 256 = 32 j x 8 lanes (gather) -> 8 og x 32 j (GEMM)
__global__ void __launch_bounds__(256) k_y_out(const float* __restrict__ x,
                                               float* __restrict__ out) {
    __shared__ __align__(16) float Ms[CH * CH];
    __shared__ float Ys[CH][33];
    __shared__ float g0s[CH];
    int b = blockIdx.y, j0 = blockIdx.x * 32, t = threadIdx.x;
    for (int i = t; i < CH * CH; i += 256) Ms[i] = g_Mt[i];
    if (t < CH) g0s[t] = g_g0[t];

    // ---- gather phase: 8 threads per j ----
    int jl = t >> 3, l8 = t & 7;
    int j = j0 + jl;
    float djf = g_d[b][j];
    float lo = fdec(g_mm[b][0]), hi = fdec(g_mm[b][1]);
    float scale = binScale(lo, hi);
    int et = (int)floorf((-djf - lo) * scale);
    et = et < 0 ? 0 : (et > NB ? NB : et);
    int k = g_binstart[b][et];
    double dj = (double)djf;
    double ed = exp(dj);
    double PAsN = g_PAs[b][NPIX], PAsk = g_PAs[b][k], PEsk = g_PEs[b][k];
    double S = (PAsN - PAsk) + dj * (double)(NPIX - k) + ed * PEsk - (double)k;

    // near-singular columns: tiny d errors are amplified by dS/dd/|S|.
    // Recompute d_j exactly (double dot) and redo S.
    if (fabs(S) < S_REFINE_T) {
        unsigned gm = 0xFFu << ((t & 31) & ~7);
        const float* xcol = x + ((size_t)b * CH) * NPIX + j;
        double pd = 0.0;
#pragma unroll
        for (int i = 0; i < 8; i++) {
            int c = l8 * 8 + i;
            pd += g_wd[c] * (double)xcol[(size_t)c * NPIX];
        }
#pragma unroll
        for (int off = 1; off < 8; off <<= 1)
            pd += __shfl_xor_sync(gm, pd, off, 8);
        dj = pd + g_cd;
        ed = exp(dj);
        S = (PAsN - PAsk) + dj * (double)(NPIX - k) + ed * PEsk - (double)k;
    }

    double inv = 1.0 / (1.5 * S);
    const double* P1k = &g_P1[b][k][0];
    const double* PAk = &g_PA[b][k][0];
    const double* PEk = &g_PE[b][k][0];
    const double* T1 = &g_P1[b][NPIX][0];
    const double* TA = &g_PA[b][NPIX][0];
#pragma unroll
    for (int i = 0; i < 8; i++) {
        int c = l8 * 8 + i;
        double y = (TA[c] - PAk[c]) + dj * (T1[c] - P1k[c]) + ed * PEk[c] - P1k[c];
        Ys[c][jl] = (float)(y * inv);
    }
    __syncthreads();

    // ---- GEMM phase: out[:, j0..j0+32] = M @ Ys + g0 ----
    int jl2 = t & 31, og = t >> 5;
    float acc[8];
#pragma unroll
    for (int i = 0; i < 8; i++) acc[i] = 0.f;
#pragma unroll
    for (int c = 0; c < CH; c++) {
        float yv = Ys[c][jl2];
        const float4* m4 = (const float4*)&Ms[c * CH + og * 8];
        float4 ma = m4[0], mb = m4[1];
        acc[0] += ma.x * yv; acc[1] += ma.y * yv; acc[2] += ma.z * yv; acc[3] += ma.w * yv;
        acc[4] += mb.x * yv; acc[5] += mb.y * yv; acc[6] += mb.z * yv; acc[7] += mb.w * yv;
    }
#pragma unroll
    for (int oo = 0; oo < 8; oo++) {
        int o = og * 8 + oo;
        out[((size_t)(b * CH + o)) * NPIX + j0 + jl2] = acc[oo] + g0s[o];
    }
}

// ---------------- launcher ----------------
extern "C" void kernel_launch(void* const* d_in, const int* in_sizes, int n_in,
                              void* d_out, int out_size) {
    (void)in_sizes; (void)n_in; (void)out_size;
    const float* x   = (const float*)d_in[0];
    const float* Wq  = (const float*)d_in[1];
    const float* bq  = (const float*)d_in[2];
    const float* Wk  = (const float*)d_in[3];
    const float* bk  = (const float*)d_in[4];
    const float* wcq = (const float*)d_in[5];
    const float* wck = (const float*)d_in[6];
    const float* Wv  = (const float*)d_in[7];
    const float* bv  = (const float*)d_in[8];
    const float* Wg  = (const float*)d_in[9];
    const float* bg  = (const float*)d_in[10];
    float* out = (float*)d_out;

    k_prep<<<CH + 1, CH>>>(Wq, bq, Wk, bk, wcq, wck, Wv, bv, Wg, bg);
    k_ad<<<(BATCH * NPIX) / 256, 256>>>(x);
    k_sort<<<BATCH, 1024>>>();
    k_scan_scalar<<<BATCH, 1024>>>();
    k_scan_vec<<<dim3(16, BATCH), 1024>>>(x);
    k_y_out<<<dim3(NPIX / 32, BATCH), 256>>>(x, out);
}

// round 6
// speedup vs baseline: 2.2292x; 2.2292x over previous
#include <cuda_runtime.h>
#include <math.h>

#define BATCH 4
#define CH 64
#define NPIX 4096
#define NB 8192
#define S_REFINE_T 64.0
#define NCHUNK 32
#define CHUNK 128

// ---------------- scratch (device globals; no allocs allowed) ----------------
__device__ float    g_a[BATCH][NPIX];
__device__ float    g_d[BATCH][NPIX];
__device__ unsigned g_mm[BATCH][2];            // encoded min/max of a per batch
__device__ int      g_binstart[BATCH][NB + 1];
__device__ int      g_perm[BATCH][NPIX];
__device__ float    g_u[CH];
__device__ float    g_w[CH];
__device__ float    g_cacd[2];
__device__ double   g_wd[CH];                  // double-folded wck.Wk
__device__ double   g_cd;                      // double wck.bk
__device__ float    g_Mt[CH * CH];             // M^T: [c][o], M = Wg @ Wv
__device__ float    g_g0[CH];                  // Wg@bv/1.5 + bg

// sorted-order per-element values
__device__ float    g_as[BATCH][NPIX];
__device__ float    g_es[BATCH][NPIX];
__device__ double   g_esd[BATCH][NPIX];
// scalar chunk sums + exclusive prefixes (double; S is ill-conditioned)
__device__ double   g_chA[BATCH][NCHUNK];
__device__ double   g_chE[BATCH][NCHUNK];
__device__ double   g_PAs[BATCH][NPIX + 1];
__device__ double   g_PEs[BATCH][NPIX + 1];
// vector exclusive prefixes (float; error enters y additively, ~1e-6 rel)
__device__ float    g_P1[BATCH][NPIX + 1][CH];
__device__ float    g_PA[BATCH][NPIX + 1][CH];
__device__ float    g_PE[BATCH][NPIX + 1][CH];

// ---------------- helpers ----------------
__device__ __forceinline__ unsigned fenc(float f) {
    unsigned u = __float_as_uint(f);
    return (u & 0x80000000u) ? ~u : (u | 0x80000000u);
}
__device__ __forceinline__ float fdec(unsigned e) {
    unsigned u = (e & 0x80000000u) ? (e & 0x7fffffffu) : ~e;
    return __uint_as_float(u);
}
__device__ __forceinline__ float binScale(float lo, float hi) {
    return (float)NB / (hi - lo + 1e-6f);
}

// ---------------- k_prep: fold weights -------------------------------------
__global__ void k_prep(const float* __restrict__ Wq, const float* __restrict__ bq,
                       const float* __restrict__ Wk, const float* __restrict__ bk,
                       const float* __restrict__ wcq, const float* __restrict__ wck,
                       const float* __restrict__ Wv, const float* __restrict__ bv,
                       const float* __restrict__ Wg, const float* __restrict__ bg) {
    int blk = blockIdx.x, t = threadIdx.x;
    if (blk < CH) {
        int o = blk;
        float acc = 0.f;
#pragma unroll 16
        for (int k = 0; k < CH; k++) acc += Wg[o * CH + k] * Wv[k * CH + t];
        g_Mt[t * CH + o] = acc;
        if (t == 0) {
            float s = 0.f;
            for (int k = 0; k < CH; k++) s += Wg[o * CH + k] * bv[k];
            g_g0[o] = s * (1.f / 1.5f) + bg[o];
        }
    } else {
        float su = 0.f;
        double swd = 0.0;
#pragma unroll
        for (int o2 = 0; o2 < 16; o2++) {
            su  += wcq[o2] * Wq[o2 * CH + t];
            swd += (double)wck[o2] * (double)Wk[o2 * CH + t];
        }
        g_u[t] = su; g_w[t] = (float)swd; g_wd[t] = swd;
        if (t == 0) {
            float ca = 0.f;
            double cdd = 0.0;
            for (int o2 = 0; o2 < 16; o2++) {
                ca += wcq[o2] * bq[o2];
                cdd += (double)wck[o2] * (double)bk[o2];
            }
            g_cacd[0] = ca; g_cacd[1] = (float)cdd; g_cd = cdd;
            for (int b = 0; b < BATCH; b++) { g_mm[b][0] = 0xFFFFFFFFu; g_mm[b][1] = 0u; }
        }
    }
}

// ---------------- k_ad: a[b,n], d[b,n] + per-batch min/max of a -------------
__global__ void __launch_bounds__(256) k_ad(const float* __restrict__ x) {
    __shared__ float su[CH], sw[CH];
    __shared__ float redmin[8], redmax[8];
    int t = threadIdx.x;
    if (t < CH) { su[t] = g_u[t]; sw[t] = g_w[t]; }
    __syncthreads();
    int gid = blockIdx.x * 256 + t;
    int b = gid >> 12, n = gid & (NPIX - 1);
    const float* xb = x + ((size_t)b * CH) * NPIX + n;
    float au = 0.f, dv = 0.f;
#pragma unroll
    for (int c = 0; c < CH; c++) {
        float xv = xb[(size_t)c * NPIX];
        au += su[c] * xv;
        dv += sw[c] * xv;
    }
    float a = au + g_cacd[0];
    float d = dv + g_cacd[1];
    g_a[b][n] = a; g_d[b][n] = d;
    float mn = a, mx = a;
#pragma unroll
    for (int off = 16; off; off >>= 1) {
        mn = fminf(mn, __shfl_xor_sync(0xffffffffu, mn, off));
        mx = fmaxf(mx, __shfl_xor_sync(0xffffffffu, mx, off));
    }
    int lane = t & 31, wid = t >> 5;
    if (lane == 0) { redmin[wid] = mn; redmax[wid] = mx; }
    __syncthreads();
    if (t == 0) {
        for (int i = 1; i < 8; i++) { mn = fminf(mn, redmin[i]); mx = fmaxf(mx, redmax[i]); }
        atomicMin(&g_mm[b][0], fenc(mn));
        atomicMax(&g_mm[b][1], fenc(mx));
    }
}

// ---------------- k_sort: counting sort of a per batch into 8192 bins -------
__global__ void __launch_bounds__(1024, 1) k_sort() {
    __shared__ unsigned bins[NB];
    __shared__ unsigned wsum[32];
    int b = blockIdx.x, t = threadIdx.x;
    int lane = t & 31, wid = t >> 5;
    for (int i = t; i < NB; i += 1024) bins[i] = 0u;
    __syncthreads();
    float lo = fdec(g_mm[b][0]), hi = fdec(g_mm[b][1]);
    float scale = binScale(lo, hi);
    for (int i = t; i < NPIX; i += 1024) {
        float a = g_a[b][i];
        int e = (int)floorf((a - lo) * scale);
        e = e < 0 ? 0 : (e > NB - 1 ? NB - 1 : e);
        atomicAdd(&bins[e], 1u);
    }
    __syncthreads();
    unsigned vals[8]; unsigned tsum = 0;
    int base = t * 8;
#pragma unroll
    for (int q = 0; q < 8; q++) { vals[q] = bins[base + q]; tsum += vals[q]; }
    unsigned inc = tsum;
#pragma unroll
    for (int off = 1; off < 32; off <<= 1) {
        unsigned nv = __shfl_up_sync(0xffffffffu, inc, off);
        if (lane >= off) inc += nv;
    }
    if (lane == 31) wsum[wid] = inc;
    __syncthreads();
    if (wid == 0) {
        unsigned ia = wsum[lane];
#pragma unroll
        for (int off = 1; off < 32; off <<= 1) {
            unsigned nv = __shfl_up_sync(0xffffffffu, ia, off);
            if (lane >= off) ia += nv;
        }
        wsum[lane] = ia;
    }
    __syncthreads();
    unsigned run = (wid ? wsum[wid - 1] : 0u) + (inc - tsum);
#pragma unroll
    for (int q = 0; q < 8; q++) {
        g_binstart[b][base + q] = (int)run;
        bins[base + q] = run;
        run += vals[q];
    }
    if (t == 0) g_binstart[b][NB] = NPIX;
    __syncthreads();
    for (int i = t; i < NPIX; i += 1024) {
        float a = g_a[b][i];
        int e = (int)floorf((a - lo) * scale);
        e = e < 0 ? 0 : (e > NB - 1 ? NB - 1 : e);
        unsigned pos = atomicAdd(&bins[e], 1u);
        g_perm[b][pos] = i;
    }
}

// ---------------- k_sA: sorted a / e^a + per-chunk double sums --------------
// grid (NCHUNK, BATCH), block CHUNK
__global__ void __launch_bounds__(CHUNK) k_sA() {
    __shared__ double rsA[4], rsE[4];
    int b = blockIdx.y, chunk = blockIdx.x, t = threadIdx.x;
    int r = chunk * CHUNK + t;
    int p = g_perm[b][r];
    float af = g_a[b][p];
    double a = (double)af;
    double e = exp(a);
    g_as[b][r] = af;
    g_es[b][r] = (float)e;
    g_esd[b][r] = e;
    // block reduce
    double sa = a, se = e;
#pragma unroll
    for (int off = 16; off; off >>= 1) {
        sa += __shfl_xor_sync(0xffffffffu, sa, off);
        se += __shfl_xor_sync(0xffffffffu, se, off);
    }
    int lane = t & 31, w = t >> 5;
    if (lane == 0) { rsA[w] = sa; rsE[w] = se; }
    __syncthreads();
    if (t == 0) {
        double tA = rsA[0] + rsA[1] + rsA[2] + rsA[3];
        double tE = rsE[0] + rsE[1] + rsE[2] + rsE[3];
        g_chA[b][chunk] = tA;
        g_chE[b][chunk] = tE;
    }
}

// ---------------- k_sC: scalar exclusive prefixes (double) ------------------
// grid (NCHUNK, BATCH), block CHUNK; each block redundantly scans chunk sums
__global__ void __launch_bounds__(CHUNK) k_sC() {
    __shared__ double offA_s, offE_s, wtA[4], wtE[4];
    int b = blockIdx.y, chunk = blockIdx.x, t = threadIdx.x;
    int lane = t & 31, w = t >> 5;
    if (t < 32) {
        double cA = g_chA[b][t], cE = g_chE[b][t];
        double iA = cA, iE = cE;
#pragma unroll
        for (int off = 1; off < 32; off <<= 1) {
            double nA = __shfl_up_sync(0xffffffffu, iA, off);
            double nE = __shfl_up_sync(0xffffffffu, iE, off);
            if (lane >= off) { iA += nA; iE += nE; }
        }
        if (t == chunk) { offA_s = iA - cA; offE_s = iE - cE; }
        if (chunk == NCHUNK - 1 && t == 31) {
            g_PAs[b][NPIX] = iA;
            g_PEs[b][NPIX] = iE;
        }
    }
    __syncthreads();
    int r = chunk * CHUNK + t;
    double a = (double)g_as[b][r];
    double e = g_esd[b][r];
    double iA = a, iE = e;
#pragma unroll
    for (int off = 1; off < 32; off <<= 1) {
        double nA = __shfl_up_sync(0xffffffffu, iA, off);
        double nE = __shfl_up_sync(0xffffffffu, iE, off);
        if (lane >= off) { iA += nA; iE += nE; }
    }
    if (lane == 31) { wtA[w] = iA; wtE[w] = iE; }
    __syncthreads();
    double wo_a = 0, wo_e = 0;
    for (int i = 0; i < 4; i++) {
        if (i < w) { wo_a += wtA[i]; wo_e += wtE[i]; }
    }
    g_PAs[b][r] = offA_s + wo_a + (iA - a);
    g_PEs[b][r] = offE_s + wo_e + (iE - e);
}

// ---------------- k_scan_vec: 64-dim float prefix vectors -------------------
// grid (16 cgroups, BATCH); block 1024 = 4 c_sub (interleaved in lanes) x 256 idx
__global__ void __launch_bounds__(1024, 1) k_scan_vec(const float* __restrict__ x) {
    __shared__ float wt[3][4][32];
    int b = blockIdx.y, cg = blockIdx.x;
    int t = threadIdx.x;
    int c_sub = t & 3, idx = t >> 2;
    int c = cg * 4 + c_sub;
    int r0 = idx * 16;
    int lane = t & 31, w = t >> 5;
    const float* xrow = x + ((size_t)(b * CH + c)) * NPIX;

    float xs[16], as[16], es[16];
    float s1 = 0.f, sa = 0.f, se = 0.f;
#pragma unroll
    for (int i = 0; i < 16; i++) {
        int r = r0 + i;
        int p = g_perm[b][r];
        float xv = xrow[p];
        float a = g_as[b][r];
        float e = g_es[b][r];
        xs[i] = xv; as[i] = a; es[i] = e;
        s1 += xv; sa += xv * a; se += xv * e;
    }
    float i1 = s1, ia = sa, ie = se;
#pragma unroll
    for (int off = 4; off < 32; off <<= 1) {
        float n1 = __shfl_up_sync(0xffffffffu, i1, off);
        float n2 = __shfl_up_sync(0xffffffffu, ia, off);
        float n3 = __shfl_up_sync(0xffffffffu, ie, off);
        if (lane >= off) { i1 += n1; ia += n2; ie += n3; }
    }
    if (lane >= 28) {
        wt[0][lane & 3][w] = i1;
        wt[1][lane & 3][w] = ia;
        wt[2][lane & 3][w] = ie;
    }
    __syncthreads();
    if (w < 4) {
        float a0 = wt[0][w][lane], a1 = wt[1][w][lane], a2 = wt[2][w][lane];
#pragma unroll
        for (int off = 1; off < 32; off <<= 1) {
            float n0 = __shfl_up_sync(0xffffffffu, a0, off);
            float n1 = __shfl_up_sync(0xffffffffu, a1, off);
            float n2 = __shfl_up_sync(0xffffffffu, a2, off);
            if (lane >= off) { a0 += n0; a1 += n1; a2 += n2; }
        }
        wt[0][w][lane] = a0; wt[1][w][lane] = a1; wt[2][w][lane] = a2;
    }
    __syncthreads();
    float r1 = (w ? wt[0][c_sub][w - 1] : 0.f) + (i1 - s1);
    float ra = (w ? wt[1][c_sub][w - 1] : 0.f) + (ia - sa);
    float re = (w ? wt[2][c_sub][w - 1] : 0.f) + (ie - se);

#pragma unroll
    for (int i = 0; i < 16; i++) {
        int r = r0 + i;
        g_P1[b][r][c] = r1;
        g_PA[b][r][c] = ra;
        g_PE[b][r][c] = re;
        float xv = xs[i];
        r1 += xv; ra += xv * as[i]; re += xv * es[i];
    }
    if (idx == 255) {
        g_P1[b][NPIX][c] = r1;
        g_PA[b][NPIX][c] = ra;
        g_PE[b][NPIX][c] = re;
    }
}

// ---------------- k_y_out: split lookup + y + fused 64x64 GEMM --------------
// grid (NPIX/32, BATCH); block 256 = 32 j x 8 lanes (gather) -> 8 og x 32 j (GEMM)
__global__ void __launch_bounds__(256) k_y_out(const float* __restrict__ x,
                                               float* __restrict__ out) {
    __shared__ __align__(16) float Ms[CH * CH];
    __shared__ float Ys[CH][33];
    __shared__ float g0s[CH];
    int b = blockIdx.y, j0 = blockIdx.x * 32, t = threadIdx.x;
    for (int i = t; i < CH * CH; i += 256) Ms[i] = g_Mt[i];
    if (t < CH) g0s[t] = g_g0[t];

    // ---- gather phase: 8 threads per j ----
    int jl = t >> 3, l8 = t & 7;
    int j = j0 + jl;
    float djf = g_d[b][j];
    float lo = fdec(g_mm[b][0]), hi = fdec(g_mm[b][1]);
    float scale = binScale(lo, hi);
    int et = (int)floorf((-djf - lo) * scale);
    et = et < 0 ? 0 : (et > NB ? NB : et);
    int k = g_binstart[b][et];
    double dj = (double)djf;
    double ed = (double)expf(djf);
    double PAsN = g_PAs[b][NPIX], PAsk = g_PAs[b][k], PEsk = g_PEs[b][k];
    double S = (PAsN - PAsk) + dj * (double)(NPIX - k) + ed * PEsk - (double)k;

    // near-singular columns: tiny d errors are amplified by dS/dd/|S|.
    // Recompute d_j exactly (double dot) and redo S.
    if (fabs(S) < S_REFINE_T) {
        unsigned gm = 0xFFu << ((t & 31) & ~7);
        const float* xcol = x + ((size_t)b * CH) * NPIX + j;
        double pd = 0.0;
#pragma unroll
        for (int i = 0; i < 8; i++) {
            int c = l8 * 8 + i;
            pd += g_wd[c] * (double)xcol[(size_t)c * NPIX];
        }
#pragma unroll
        for (int off = 1; off < 8; off <<= 1)
            pd += __shfl_xor_sync(gm, pd, off, 8);
        dj = pd + g_cd;
        ed = exp(dj);
        S = (PAsN - PAsk) + dj * (double)(NPIX - k) + ed * PEsk - (double)k;
    }

    float inv = (float)(1.0 / (1.5 * S));
    float djc = (float)dj, edc = (float)ed;
    const float4* P1k = (const float4*)&g_P1[b][k][0];
    const float4* PAk = (const float4*)&g_PA[b][k][0];
    const float4* PEk = (const float4*)&g_PE[b][k][0];
    const float4* T1 = (const float4*)&g_P1[b][NPIX][0];
    const float4* TA = (const float4*)&g_PA[b][NPIX][0];
#pragma unroll
    for (int q = 0; q < 2; q++) {
        int cv = l8 * 2 + q;
        float4 p1 = P1k[cv], pa = PAk[cv], pe = PEk[cv], t1 = T1[cv], ta = TA[cv];
        int c0 = cv * 4;
        Ys[c0 + 0][jl] = ((ta.x - pa.x) + djc * (t1.x - p1.x) + edc * pe.x - p1.x) * inv;
        Ys[c0 + 1][jl] = ((ta.y - pa.y) + djc * (t1.y - p1.y) + edc * pe.y - p1.y) * inv;
        Ys[c0 + 2][jl] = ((ta.z - pa.z) + djc * (t1.z - p1.z) + edc * pe.z - p1.z) * inv;
        Ys[c0 + 3][jl] = ((ta.w - pa.w) + djc * (t1.w - p1.w) + edc * pe.w - p1.w) * inv;
    }
    __syncthreads();

    // ---- GEMM phase: out[:, j0..j0+32] = M @ Ys + g0 ----
    int jl2 = t & 31, og = t >> 5;
    float acc[8];
#pragma unroll
    for (int i = 0; i < 8; i++) acc[i] = 0.f;
#pragma unroll
    for (int c = 0; c < CH; c++) {
        float yv = Ys[c][jl2];
        const float4* m4 = (const float4*)&Ms[c * CH + og * 8];
        float4 ma = m4[0], mb = m4[1];
        acc[0] += ma.x * yv; acc[1] += ma.y * yv; acc[2] += ma.z * yv; acc[3] += ma.w * yv;
        acc[4] += mb.x * yv; acc[5] += mb.y * yv; acc[6] += mb.z * yv; acc[7] += mb.w * yv;
    }
#pragma unroll
    for (int oo = 0; oo < 8; oo++) {
        int o = og * 8 + oo;
        out[((size_t)(b * CH + o)) * NPIX + j0 + jl2] = acc[oo] + g0s[o];
    }
}

// ---------------- launcher ----------------
extern "C" void kernel_launch(void* const* d_in, const int* in_sizes, int n_in,
                              void* d_out, int out_size) {
    (void)in_sizes; (void)n_in; (void)out_size;
    const float* x   = (const float*)d_in[0];
    const float* Wq  = (const float*)d_in[1];
    const float* bq  = (const float*)d_in[2];
    const float* Wk  = (const float*)d_in[3];
    const float* bk  = (const float*)d_in[4];
    const float* wcq = (const float*)d_in[5];
    const float* wck = (const float*)d_in[6];
    const float* Wv  = (const float*)d_in[7];
    const float* bv  = (const float*)d_in[8];
    const float* Wg  = (const float*)d_in[9];
    const float* bg  = (const float*)d_in[10];
    float* out = (float*)d_out;

    k_prep<<<CH + 1, CH>>>(Wq, bq, Wk, bk, wcq, wck, Wv, bv, Wg, bg);
    k_ad<<<(BATCH * NPIX) / 256, 256>>>(x);
    k_sort<<<BATCH, 1024>>>();
    k_sA<<<dim3(NCHUNK, BATCH), CHUNK>>>();
    k_sC<<<dim3(NCHUNK, BATCH), CHUNK>>>();
    k_scan_vec<<<dim3(16, BATCH), 1024>>>(x);
    k_y_out<<<dim3(NPIX / 32, BATCH), 256>>>(x, out);
}